// round 1
// baseline (speedup 1.0000x reference)
#include <cuda_runtime.h>

#define NN 100000
#define NE 1600000
#define HD 64
#define BN_EPS 1e-5f

// ---------------- scratch (device globals; no runtime allocation) ----------
static __device__ __align__(16) float g_h[NN * HD];   // running node features
static __device__ __align__(16) float g_z[NN * HD];   // h + aggregation
static __device__ __align__(16) float g_y[NN * HD];   // MLP output (pre-BN)
static __device__ int    g_srcs[NE];                  // src sorted by dst (CSR)
static __device__ float4 g_ef[NE];                    // edge features sorted by dst
static __device__ int    g_deg[NN];
static __device__ int    g_rowptr[NN + 1];
static __device__ int    g_wcur[NN];
static __device__ int    g_bsum[32];
static __device__ float  g_stats[2 * HD];             // per-channel sum / sumsq
static __device__ float  g_scale[HD];
static __device__ float  g_shift[HD];

typedef unsigned long long u64;

__device__ __forceinline__ u64 pk2(float x, float y) {
    u64 r; asm("mov.b64 %0,{%1,%2};" : "=l"(r) : "f"(x), "f"(y)); return r;
}
__device__ __forceinline__ float2 upk2(u64 a) {
    float2 r; asm("mov.b64 {%0,%1},%2;" : "=f"(r.x), "=f"(r.y) : "l"(a)); return r;
}
__device__ __forceinline__ u64 ffma2(u64 a, u64 b, u64 c) {
    u64 d; asm("fma.rn.f32x2 %0,%1,%2,%3;" : "=l"(d) : "l"(a), "l"(b), "l"(c)); return d;
}

// ---------------- preprocessing --------------------------------------------

__global__ void k_copy_h(const float4* __restrict__ node_feat) {
    int i = blockIdx.x * blockDim.x + threadIdx.x;
    if (i < NN * (HD / 4)) reinterpret_cast<float4*>(g_h)[i] = node_feat[i];
}

__global__ void k_zero_deg() {
    int i = blockIdx.x * blockDim.x + threadIdx.x;
    if (i < NN) g_deg[i] = 0;
}

__global__ void k_hist(const int* __restrict__ dst) {
    int i = blockIdx.x * blockDim.x + threadIdx.x;
    if (i < NE) atomicAdd(&g_deg[dst[i]], 1);
}

// block scan over chunks of 4096 (512 threads x 8 items)
__global__ void k_scan1() {
    __shared__ int s[512];
    int tid = threadIdx.x;
    int base = blockIdx.x * 4096 + tid * 8;
    int items[8];
    int t = 0;
#pragma unroll
    for (int j = 0; j < 8; ++j) {
        int idx = base + j;
        int v = (idx < NN) ? g_deg[idx] : 0;
        items[j] = v; t += v;
    }
    s[tid] = t;
    __syncthreads();
    for (int off = 1; off < 512; off <<= 1) {
        int v = (tid >= off) ? s[tid - off] : 0;
        __syncthreads();
        s[tid] += v;
        __syncthreads();
    }
    int run = s[tid] - t;  // exclusive prefix for this thread
#pragma unroll
    for (int j = 0; j < 8; ++j) {
        int idx = base + j;
        if (idx < NN) g_rowptr[idx] = run;
        run += items[j];
    }
    if (tid == 511) g_bsum[blockIdx.x] = s[511];
}

__global__ void k_scan2() {
    int run = 0;
    for (int i = 0; i < 25; ++i) { int v = g_bsum[i]; g_bsum[i] = run; run += v; }
}

__global__ void k_scan3() {
    int i = blockIdx.x * blockDim.x + threadIdx.x;
    if (i < NN) {
        int v = g_rowptr[i] + g_bsum[i >> 12];
        g_rowptr[i] = v;
        g_wcur[i] = v;
    }
    if (i == 0) g_rowptr[NN] = NE;
}

__global__ void k_scatter(const int* __restrict__ src, const int* __restrict__ dst,
                          const float4* __restrict__ edge_feat) {
    int i = blockIdx.x * blockDim.x + threadIdx.x;
    if (i >= NE) return;
    int d = dst[i];
    int p = atomicAdd(&g_wcur[d], 1);
    g_srcs[p] = src[i];
    g_ef[p]   = edge_feat[i];
}

// ---------------- per-layer kernels ----------------------------------------

// K1: one warp per node, lane owns channels (lane, lane+32).
// z[n] = h[n] + sum_{edges into n} relu(h[src] + edge_feat@We + be)
__global__ void k1_gather(const float* __restrict__ We, const float* __restrict__ be) {
    int n    = (blockIdx.x * blockDim.x + threadIdx.x) >> 5;
    int lane = threadIdx.x & 31;
    if (n >= NN) return;
    int c0 = lane, c1 = lane + 32;

    float w00 = We[c0], w10 = We[64 + c0], w20 = We[128 + c0], w30 = We[192 + c0];
    float w01 = We[c1], w11 = We[64 + c1], w21 = We[128 + c1], w31 = We[192 + c1];
    float bb0 = be[c0], bb1 = be[c1];

    int beg = g_rowptr[n], end = g_rowptr[n + 1];
    float acc0 = g_h[n * 64 + c0];
    float acc1 = g_h[n * 64 + c1];

    for (int j = beg; j < end; ++j) {
        int s = g_srcs[j];
        float4 f = g_ef[j];
        float hv0 = g_h[s * 64 + c0];
        float hv1 = g_h[s * 64 + c1];
        float e0 = fmaf(f.x, w00, fmaf(f.y, w10, fmaf(f.z, w20, fmaf(f.w, w30, bb0))));
        float e1 = fmaf(f.x, w01, fmaf(f.y, w11, fmaf(f.z, w21, fmaf(f.w, w31, bb1))));
        acc0 += fmaxf(hv0 + e0, 0.f);
        acc1 += fmaxf(hv1 + e1, 0.f);
    }
    g_z[n * 64 + c0] = acc0;
    g_z[n * 64 + c1] = acc1;
}

__global__ void k_zero_stats() {
    g_stats[threadIdx.x] = 0.f;
}

// K2: fused y = relu(z@W1+b1)@W2+b2 over a 64-row tile, plus BN batch stats.
// A operands stored pre-splatted as f32x2 pairs in SMEM; packed fma.rn.f32x2.
#define K2_SMEM (64 * 66 * 8 + 64 * 64 * 4 + 128 * 4)
__global__ void __launch_bounds__(256, 4) k2_mlp(
    const float* __restrict__ W1, const float* __restrict__ b1,
    const float* __restrict__ W2, const float* __restrict__ b2) {
    extern __shared__ char smem_raw[];
    u64 (*sA)[66] = reinterpret_cast<u64(*)[66]>(smem_raw);
    float* sW   = reinterpret_cast<float*>(smem_raw + 64 * 66 * sizeof(u64));
    float* ssum = sW + 64 * 64;
    float* ssq  = ssum + 64;

    int tid = threadIdx.x;
    int rb  = blockIdx.x * 64;
    if (tid < 64) { ssum[tid] = 0.f; ssq[tid] = 0.f; }

    int tx = tid & 15, ty = tid >> 4;
    int c0 = tx * 4, r0 = ty * 4;

    // load z tile transposed + splatted: sA[k][r] = (z[r][k], z[r][k])
    for (int itr = 0; itr < 4; ++itr) {
        int r = ty + itr * 16;
        float4 v = make_float4(0.f, 0.f, 0.f, 0.f);
        if (rb + r < NN) v = *reinterpret_cast<const float4*>(g_z + (rb + r) * 64 + c0);
        sA[c0 + 0][r] = pk2(v.x, v.x);
        sA[c0 + 1][r] = pk2(v.y, v.y);
        sA[c0 + 2][r] = pk2(v.z, v.z);
        sA[c0 + 3][r] = pk2(v.w, v.w);
    }
    // load W1
    for (int itr = 0; itr < 4; ++itr) {
        int idx = tid + itr * 256;
        reinterpret_cast<float4*>(sW)[idx] = __ldg(reinterpret_cast<const float4*>(W1) + idx);
    }
    __syncthreads();

    // ---- GEMM1 ----
    u64 a00 = 0, a01 = 0, a10 = 0, a11 = 0, a20 = 0, a21 = 0, a30 = 0, a31 = 0;
#pragma unroll 8
    for (int k = 0; k < 64; ++k) {
        ulonglong2 p01 = *reinterpret_cast<ulonglong2*>(&sA[k][r0]);
        ulonglong2 p23 = *reinterpret_cast<ulonglong2*>(&sA[k][r0 + 2]);
        ulonglong2 w   = *reinterpret_cast<ulonglong2*>(&sW[k * 64 + c0]);
        a00 = ffma2(p01.x, w.x, a00); a01 = ffma2(p01.x, w.y, a01);
        a10 = ffma2(p01.y, w.x, a10); a11 = ffma2(p01.y, w.y, a11);
        a20 = ffma2(p23.x, w.x, a20); a21 = ffma2(p23.x, w.y, a21);
        a30 = ffma2(p23.y, w.x, a30); a31 = ffma2(p23.y, w.y, a31);
    }
    float4 bb1 = __ldg(reinterpret_cast<const float4*>(b1 + c0));
    float tt[4][4];
    { float2 u = upk2(a00); tt[0][0] = u.x; tt[0][1] = u.y; }
    { float2 u = upk2(a01); tt[0][2] = u.x; tt[0][3] = u.y; }
    { float2 u = upk2(a10); tt[1][0] = u.x; tt[1][1] = u.y; }
    { float2 u = upk2(a11); tt[1][2] = u.x; tt[1][3] = u.y; }
    { float2 u = upk2(a20); tt[2][0] = u.x; tt[2][1] = u.y; }
    { float2 u = upk2(a21); tt[2][2] = u.x; tt[2][3] = u.y; }
    { float2 u = upk2(a30); tt[3][0] = u.x; tt[3][1] = u.y; }
    { float2 u = upk2(a31); tt[3][2] = u.x; tt[3][3] = u.y; }
#pragma unroll
    for (int i = 0; i < 4; ++i) {
        tt[i][0] = fmaxf(tt[i][0] + bb1.x, 0.f);
        tt[i][1] = fmaxf(tt[i][1] + bb1.y, 0.f);
        tt[i][2] = fmaxf(tt[i][2] + bb1.z, 0.f);
        tt[i][3] = fmaxf(tt[i][3] + bb1.w, 0.f);
    }
    __syncthreads();  // everyone done reading sA / sW

    // store t transposed + splatted; reload sW with W2
#pragma unroll
    for (int i = 0; i < 4; ++i)
#pragma unroll
        for (int j = 0; j < 4; ++j)
            sA[c0 + j][r0 + i] = pk2(tt[i][j], tt[i][j]);
    for (int itr = 0; itr < 4; ++itr) {
        int idx = tid + itr * 256;
        reinterpret_cast<float4*>(sW)[idx] = __ldg(reinterpret_cast<const float4*>(W2) + idx);
    }
    __syncthreads();

    // ---- GEMM2 ----
    a00 = a01 = a10 = a11 = a20 = a21 = a30 = a31 = 0;
#pragma unroll 8
    for (int k = 0; k < 64; ++k) {
        ulonglong2 p01 = *reinterpret_cast<ulonglong2*>(&sA[k][r0]);
        ulonglong2 p23 = *reinterpret_cast<ulonglong2*>(&sA[k][r0 + 2]);
        ulonglong2 w   = *reinterpret_cast<ulonglong2*>(&sW[k * 64 + c0]);
        a00 = ffma2(p01.x, w.x, a00); a01 = ffma2(p01.x, w.y, a01);
        a10 = ffma2(p01.y, w.x, a10); a11 = ffma2(p01.y, w.y, a11);
        a20 = ffma2(p23.x, w.x, a20); a21 = ffma2(p23.x, w.y, a21);
        a30 = ffma2(p23.y, w.x, a30); a31 = ffma2(p23.y, w.y, a31);
    }
    float4 bb2 = __ldg(reinterpret_cast<const float4*>(b2 + c0));
    float yy[4][4];
    { float2 u = upk2(a00); yy[0][0] = u.x + bb2.x; yy[0][1] = u.y + bb2.y; }
    { float2 u = upk2(a01); yy[0][2] = u.x + bb2.z; yy[0][3] = u.y + bb2.w; }
    { float2 u = upk2(a10); yy[1][0] = u.x + bb2.x; yy[1][1] = u.y + bb2.y; }
    { float2 u = upk2(a11); yy[1][2] = u.x + bb2.z; yy[1][3] = u.y + bb2.w; }
    { float2 u = upk2(a20); yy[2][0] = u.x + bb2.x; yy[2][1] = u.y + bb2.y; }
    { float2 u = upk2(a21); yy[2][2] = u.x + bb2.z; yy[2][3] = u.y + bb2.w; }
    { float2 u = upk2(a30); yy[3][0] = u.x + bb2.x; yy[3][1] = u.y + bb2.y; }
    { float2 u = upk2(a31); yy[3][2] = u.x + bb2.z; yy[3][3] = u.y + bb2.w; }

    // write y + accumulate stats
#pragma unroll
    for (int i = 0; i < 4; ++i) {
        int r = rb + r0 + i;
        if (r < NN) {
            float4 v = make_float4(yy[i][0], yy[i][1], yy[i][2], yy[i][3]);
            *reinterpret_cast<float4*>(g_y + r * 64 + c0) = v;
        }
    }
#pragma unroll
    for (int j = 0; j < 4; ++j) {
        float sj = 0.f, qj = 0.f;
#pragma unroll
        for (int i = 0; i < 4; ++i) {
            if (rb + r0 + i < NN) { sj += yy[i][j]; qj += yy[i][j] * yy[i][j]; }
        }
        atomicAdd(&ssum[c0 + j], sj);
        atomicAdd(&ssq[c0 + j], qj);
    }
    __syncthreads();
    if (tid < 64) {
        atomicAdd(&g_stats[tid], ssum[tid]);
        atomicAdd(&g_stats[64 + tid], ssq[tid]);
    }
}

__global__ void k3_bn(const float* __restrict__ gamma, const float* __restrict__ beta) {
    int c = threadIdx.x;
    float mean = g_stats[c] * (1.f / NN);
    float var  = g_stats[64 + c] * (1.f / NN) - mean * mean;
    float inv  = rsqrtf(var + BN_EPS);
    float sc   = gamma[c] * inv;
    g_scale[c] = sc;
    g_shift[c] = beta[c] - mean * sc;
}

// K4: h = relu(y*scale + shift) + h   (writes g_h, or d_out on last layer)
__global__ void k4_post(float* __restrict__ out_final, int last) {
    int i = blockIdx.x * blockDim.x + threadIdx.x;  // float4 index
    if (i >= NN * (HD / 4)) return;
    int c0 = (i & 15) * 4;
    float4 y  = reinterpret_cast<const float4*>(g_y)[i];
    float4 h  = reinterpret_cast<const float4*>(g_h)[i];
    float4 sc = *reinterpret_cast<const float4*>(g_scale + c0);
    float4 sh = *reinterpret_cast<const float4*>(g_shift + c0);
    float4 o;
    o.x = fmaxf(fmaf(y.x, sc.x, sh.x), 0.f) + h.x;
    o.y = fmaxf(fmaf(y.y, sc.y, sh.y), 0.f) + h.y;
    o.z = fmaxf(fmaf(y.z, sc.z, sh.z), 0.f) + h.z;
    o.w = fmaxf(fmaf(y.w, sc.w, sh.w), 0.f) + h.w;
    float4* dst = last ? reinterpret_cast<float4*>(out_final)
                       : reinterpret_cast<float4*>(g_h);
    dst[i] = o;
}

// ---------------- launch ----------------------------------------------------

extern "C" void kernel_launch(void* const* d_in, const int* in_sizes, int n_in,
                              void* d_out, int out_size) {
    const float* node_feat = (const float*)d_in[0];
    const float* edge_feat = (const float*)d_in[1];
    const int*   src       = (const int*)d_in[2];
    const int*   dst       = (const int*)d_in[3];
    const float* We        = (const float*)d_in[4];
    const float* be        = (const float*)d_in[5];
    const float* W1        = (const float*)d_in[6];
    const float* b1        = (const float*)d_in[7];
    const float* W2        = (const float*)d_in[8];
    const float* b2        = (const float*)d_in[9];
    const float* gamma     = (const float*)d_in[10];
    const float* beta      = (const float*)d_in[11];
    float* out = (float*)d_out;

    cudaFuncSetAttribute(k2_mlp, cudaFuncAttributeMaxDynamicSharedMemorySize, K2_SMEM);

    const int T = 256;
    k_copy_h<<<(NN * 16 + T - 1) / T, T>>>(reinterpret_cast<const float4*>(node_feat));
    k_zero_deg<<<(NN + T - 1) / T, T>>>();
    k_hist<<<(NE + T - 1) / T, T>>>(dst);
    k_scan1<<<25, 512>>>();
    k_scan2<<<1, 1>>>();
    k_scan3<<<(NN + T - 1) / T, T>>>();
    k_scatter<<<(NE + T - 1) / T, T>>>(src, dst, reinterpret_cast<const float4*>(edge_feat));

    for (int l = 0; l < 4; ++l) {
        k1_gather<<<(NN * 32 + T - 1) / T, T>>>(We, be);
        k_zero_stats<<<1, 128>>>();
        k2_mlp<<<(NN + 63) / 64, 256, K2_SMEM>>>(W1 + l * HD * HD, b1 + l * HD,
                                                 W2 + l * HD * HD, b2 + l * HD);
        k3_bn<<<1, 64>>>(gamma + l * HD, beta + l * HD);
        k4_post<<<(NN * 16 + T - 1) / T, T>>>(out, l == 3 ? 1 : 0);
    }
}